// round 3
// baseline (speedup 1.0000x reference)
#include <cuda_runtime.h>
#include <mma.h>
#include <cstdint>

using namespace nvcuda;

#define N_VEC  16384
#define VOCAB  4096
#define C_DIM  256
#define KEXT   768          // 3 * 256 (split-GEMM K)

// ---------------------------------------------------------------------------
// Scratch (device globals: allocation-free per harness rules)
__device__ float g_Aext[N_VEC * KEXT];   // [Ah | Al | Ah]  48 MB
__device__ float g_Bext[VOCAB * KEXT];   // [Bh | Bh | Bl]  12 MB
__device__ float g_halfnorm[VOCAB];      // 0.5 * ||e_v||^2  (exact fp32)
__device__ float g_bestscore[N_VEC];
__device__ int   g_bestidx[N_VEC];
__device__ float g_partial[4096];

// ---------------------------------------------------------------------------
__device__ __forceinline__ uint32_t smem_u32(const void* p) {
    uint32_t a;
    asm("{ .reg .u64 t; cvta.to.shared.u64 t, %1; cvt.u32.u64 %0, t; }"
        : "=r"(a) : "l"(p));
    return a;
}
__device__ __forceinline__ float tf32r(float x) {
    uint32_t u;
    asm("cvt.rna.tf32.f32 %0, %1;" : "=r"(u) : "f"(x));
    return __uint_as_float(u);
}
#define CP_ASYNC16(saddr, gptr) \
    asm volatile("cp.async.cg.shared.global [%0], [%1], 16;" \
                 :: "r"(saddr), "l"(gptr) : "memory")
#define CP_COMMIT() asm volatile("cp.async.commit_group;" ::: "memory")
#define CP_WAIT1()  asm volatile("cp.async.wait_group 1;" ::: "memory")
#define CP_WAIT0()  asm volatile("cp.async.wait_group 0;" ::: "memory")

// ---------------------------------------------------------------------------
// prep: transpose h (B,C,H,W)->(N,C), tf32 split, write [Ah|Al|Ah]
// grid (32,8,16), block (32,8)
__global__ void prep_h_kernel(const float* __restrict__ h) {
    __shared__ float tile[32][33];
    int b = blockIdx.z, ct = blockIdx.y, st = blockIdx.x;
    int c0 = ct * 32, s0 = st * 32;
    int tx = threadIdx.x, ty = threadIdx.y;

    const float* src = h + ((size_t)b * C_DIM + c0) * 1024 + s0;
    #pragma unroll
    for (int i = 0; i < 32; i += 8)
        tile[ty + i][tx] = src[(size_t)(ty + i) * 1024 + tx];
    __syncthreads();
    size_t rowbase = (size_t)b * 1024 + s0;
    #pragma unroll
    for (int i = 0; i < 32; i += 8) {
        float x = tile[tx][ty + i];
        float fh = tf32r(x);
        float fl = tf32r(x - fh);
        size_t rb = (rowbase + ty + i) * KEXT + c0 + tx;
        g_Aext[rb]       = fh;
        g_Aext[rb + 256] = fl;
        g_Aext[rb + 512] = fh;
    }
}

// prep: embedding tf32 split -> [Bh|Bh|Bl], plus exact 0.5||e||^2
__global__ void prep_emb_kernel(const float* __restrict__ emb) {
    int v = blockIdx.x, t = threadIdx.x;
    float x = emb[v * C_DIM + t];
    float fh = tf32r(x);
    float fl = tf32r(x - fh);
    size_t rb = (size_t)v * KEXT + t;
    g_Bext[rb]       = fh;
    g_Bext[rb + 256] = fh;
    g_Bext[rb + 512] = fl;

    float s = x * x;
    __shared__ float sm[8];
    #pragma unroll
    for (int o = 16; o > 0; o >>= 1) s += __shfl_down_sync(0xFFFFFFFFu, s, o);
    if ((t & 31) == 0) sm[t >> 5] = s;
    __syncthreads();
    if (t == 0) {
        float tot = 0.f;
        #pragma unroll
        for (int i = 0; i < 8; i++) tot += sm[i];
        g_halfnorm[v] = 0.5f * tot;
    }
}

// deterministic sum(h^2) partials
__global__ void sumsq_kernel(const float* __restrict__ h) {
    int t = threadIdx.x;
    size_t base = (size_t)blockIdx.x * 1024;
    float s = 0.f;
    #pragma unroll
    for (int i = t; i < 1024; i += 256) { float x = h[base + i]; s += x * x; }
    __shared__ float sm[8];
    #pragma unroll
    for (int o = 16; o > 0; o >>= 1) s += __shfl_down_sync(0xFFFFFFFFu, s, o);
    if ((t & 31) == 0) sm[t >> 5] = s;
    __syncthreads();
    if (t == 0) {
        float tot = 0.f;
        #pragma unroll
        for (int i = 0; i < 8; i++) tot += sm[i];
        g_partial[blockIdx.x] = tot;
    }
}

// ---------------------------------------------------------------------------
// WMMA tf32 GEMM + fused argmax.
// grid = 128 CTAs (128 M-rows each), 256 threads (8 warps, 4x2).
// smem layout (floats):
#define LDA   36                 // 32 + 4 pad (16B-aligned rows)
#define LDC   132                // 128 + 4
#define F_AS0 0
#define F_BS0 (128 * LDA)        // 4608
#define F_AS1 (2 * 128 * LDA)    // 9216
#define F_BS1 (3 * 128 * LDA)    // 13824
#define F_CS  (4 * 128 * LDA)    // 18432
#define SMEM_FLOATS (F_CS + 128 * LDC)
#define SMEM_BYTES  (SMEM_FLOATS * 4)   // 141,312 B

__global__ __launch_bounds__(256, 1) void vq_wmma_kernel() {
    extern __shared__ float smf[];
    const uint32_t sb = smem_u32(smf);
    const int tid = threadIdx.x;
    const int w = tid >> 5;
    const int m0 = blockIdx.x * 128;

    const int wm = w & 3;        // row group: rows wm*32 .. +31
    const int wn = w >> 2;       // col group: cols wn*64 .. +63

    // chunk loader mapping: thread -> (row, kq)
    const int lr = tid >> 3;       // 0..31 (x4 iters -> 128 rows)
    const int lk = (tid & 7) * 4;  // float offset within 32-wide chunk

    // per-thread running argmax over its (row, half) lane of the C tile
    const int srow  = tid >> 1;
    const int shalf = tid & 1;
    float best = -3.402823466e38f;
    int   bidx = 0;

    wmma::fragment<wmma::accumulator, 16, 16, 8, float> acc[2][4];

    for (int vt = 0; vt < 32; vt++) {
        const int v0 = vt << 7;
        #pragma unroll
        for (int i = 0; i < 2; i++)
            #pragma unroll
            for (int j = 0; j < 4; j++)
                wmma::fill_fragment(acc[i][j], 0.f);

        const float* Abase = g_Aext + (size_t)m0 * KEXT;
        const float* Bbase = g_Bext + (size_t)v0 * KEXT;

        // ---- prologue: chunk 0 into stage 0 ----
        {
            #pragma unroll
            for (int i = 0; i < 4; i++) {
                int r = lr + i * 32;
                uint32_t sa = sb + (F_AS0 + r * LDA + lk) * 4;
                uint32_t sbm = sb + (F_BS0 + r * LDA + lk) * 4;
                CP_ASYNC16(sa,  Abase + (size_t)r * KEXT + lk);
                CP_ASYNC16(sbm, Bbase + (size_t)r * KEXT + lk);
            }
            CP_COMMIT();
        }

        for (int ck = 0; ck < 24; ck++) {
            const int s  = ck & 1;
            // issue next chunk into the other stage
            if (ck < 23) {
                const int k0 = (ck + 1) * 32;
                const int fs = (s ^ 1) ? F_AS1 : F_AS0;
                const int fb = (s ^ 1) ? F_BS1 : F_BS0;
                #pragma unroll
                for (int i = 0; i < 4; i++) {
                    int r = lr + i * 32;
                    uint32_t sa  = sb + (fs + r * LDA + lk) * 4;
                    uint32_t sbm = sb + (fb + r * LDA + lk) * 4;
                    CP_ASYNC16(sa,  Abase + (size_t)r * KEXT + k0 + lk);
                    CP_ASYNC16(sbm, Bbase + (size_t)r * KEXT + k0 + lk);
                }
                CP_COMMIT();
                CP_WAIT1();
            } else {
                CP_WAIT0();
            }
            __syncthreads();

            const float* As = smf + (s ? F_AS1 : F_AS0);
            const float* Bs = smf + (s ? F_BS1 : F_BS0);

            #pragma unroll
            for (int ks = 0; ks < 4; ks++) {
                const int k = ks * 8;
                wmma::fragment<wmma::matrix_a, 16, 16, 8,
                               wmma::precision::tf32, wmma::row_major> af[2];
                wmma::fragment<wmma::matrix_b, 16, 16, 8,
                               wmma::precision::tf32, wmma::col_major> bf[4];
                #pragma unroll
                for (int i = 0; i < 2; i++)
                    wmma::load_matrix_sync(af[i], As + (wm * 32 + i * 16) * LDA + k, LDA);
                #pragma unroll
                for (int j = 0; j < 4; j++)
                    wmma::load_matrix_sync(bf[j], Bs + (wn * 64 + j * 16) * LDA + k, LDA);
                #pragma unroll
                for (int i = 0; i < 2; i++)
                    #pragma unroll
                    for (int j = 0; j < 4; j++)
                        wmma::mma_sync(acc[i][j], af[i], bf[j], acc[i][j]);
            }
            __syncthreads();   // protect stage before it is overwritten
        }

        // ---- epilogue: spill C tile, fuse bias + running argmax ----
        float* Cs = smf + F_CS;
        #pragma unroll
        for (int i = 0; i < 2; i++)
            #pragma unroll
            for (int j = 0; j < 4; j++)
                wmma::store_matrix_sync(Cs + (wm * 32 + i * 16) * LDC + wn * 64 + j * 16,
                                        acc[i][j], LDC, wmma::mem_row_major);
        __syncthreads();

        {
            const float* crow = Cs + srow * LDC + shalf * 64;
            const int vb = v0 + shalf * 64;
            #pragma unroll 8
            for (int c = 0; c < 64; c++) {
                float sc = crow[c] - __ldg(&g_halfnorm[vb + c]);
                if (sc > best) { best = sc; bidx = vb + c; }
            }
        }
        __syncthreads();   // done reading Cs before next tile overwrites
    }

    // merge the two halves of each row
    __shared__ float rs[256];
    __shared__ int   ri[256];
    rs[tid] = best; ri[tid] = bidx;
    __syncthreads();
    if (tid < 128) {
        float s0 = rs[2 * tid],     s1 = rs[2 * tid + 1];
        int   i0 = ri[2 * tid],     i1 = ri[2 * tid + 1];
        bool take0 = (s0 > s1) || (s0 == s1 && i0 < i1);
        g_bestscore[m0 + tid] = take0 ? s0 : s1;
        g_bestidx[m0 + tid]   = take0 ? i0 : i1;
    }
}

// ---------------------------------------------------------------------------
// z_q gather in (B,C,H,W) layout
__global__ void gather_kernel(const float* __restrict__ emb, float* __restrict__ out) {
    int bc = blockIdx.x;
    int b = bc >> 8, c = bc & 255;
    int t = threadIdx.x;
    #pragma unroll
    for (int u = 0; u < 4; u++) {
        int sp = t + u * 256;
        int n = b * 1024 + sp;
        out[(size_t)bc * 1024 + sp] = __ldg(&emb[(size_t)g_bestidx[n] * C_DIM + c]);
    }
}

__global__ void indices_kernel(float* __restrict__ out) {
    int n = blockIdx.x * 256 + threadIdx.x;
    out[4194304 + n] = (float)g_bestidx[n];
}

__global__ void loss_kernel(float* __restrict__ out) {
    __shared__ float sm[256];
    int t = threadIdx.x;
    float s1 = 0.f, s2 = 0.f;
    for (int i = t; i < 4096; i += 256)  s1 += g_partial[i];
    for (int i = t; i < N_VEC; i += 256) s2 += g_bestscore[i];
    sm[t] = s1 - 2.f * s2;
    __syncthreads();
    #pragma unroll
    for (int o = 128; o > 0; o >>= 1) {
        if (t < o) sm[t] += sm[t + o];
        __syncthreads();
    }
    if (t == 0) out[4210688] = sm[0] / 4194304.f;
}

// ---------------------------------------------------------------------------
extern "C" void kernel_launch(void* const* d_in, const int* in_sizes, int n_in,
                              void* d_out, int out_size) {
    const float* h   = (const float*)d_in[0];   // (16,256,32,32) fp32
    const float* emb = (const float*)d_in[1];   // (4096,256) fp32
    float* out = (float*)d_out;

    static bool attr_set = false;
    if (!attr_set) {
        cudaFuncSetAttribute(vq_wmma_kernel,
                             cudaFuncAttributeMaxDynamicSharedMemorySize, SMEM_BYTES);
        attr_set = true;
    }

    dim3 tgrid(32, 8, 16), tblk(32, 8);
    prep_h_kernel<<<tgrid, tblk>>>(h);
    prep_emb_kernel<<<VOCAB, 256>>>(emb);
    sumsq_kernel<<<4096, 256>>>(h);

    vq_wmma_kernel<<<128, 256, SMEM_BYTES>>>();

    gather_kernel<<<4096, 256>>>(emb, out);
    indices_kernel<<<N_VEC / 256, 256>>>(out);
    loss_kernel<<<1, 256>>>(out);
}

// round 4
// speedup vs baseline: 5.1847x; 5.1847x over previous
#include <cuda_runtime.h>
#include <cuda_fp16.h>
#include <mma.h>
#include <cstdint>
#include <cfloat>

using namespace nvcuda;

#define N_VEC  16384
#define VOCAB  4096
#define C_DIM  256

// margin constants (rigorous fp16-quantization bound + slacks)
#define MCOEF      1.06e-3f   // >= 2.01 * 2^-11
#define ACC_SLACK  0.02f      // fp32 accumulation-order rounding slack
#define TSLK       0.17f      // ACC_SLACK + fp16 score-storage slack

// ---------------------------------------------------------------------------
// device-global scratch (no allocations allowed)
__device__ float  g_hflat[N_VEC * C_DIM];     // h transposed (N,C) fp32, 16MB
__device__ __half g_A16[N_VEC * C_DIM];       // fp16 copy, 8MB
__device__ __half g_B16[VOCAB * C_DIM];       // fp16 codebook, 2MB
__device__ __half g_S16[(size_t)N_VEC * VOCAB]; // approx scores, 128MB
__device__ float  g_halfnorm[VOCAB];          // 0.5*||e||^2 exact
__device__ float  g_enorm[VOCAB];             // ||e||
__device__ float  g_xnorm[N_VEC];             // ||x||
__device__ float  g_maxlower[N_VEC];
__device__ float  g_bestscore[N_VEC];
__device__ int    g_bestidx[N_VEC];
__device__ float  g_partial[4096];

// ---------------------------------------------------------------------------
__device__ __forceinline__ uint32_t smem_u32(const void* p) {
    uint32_t a;
    asm("{ .reg .u64 t; cvta.to.shared.u64 t, %1; cvt.u32.u64 %0, t; }"
        : "=r"(a) : "l"(p));
    return a;
}
#define CP_ASYNC16(saddr, gptr) \
    asm volatile("cp.async.cg.shared.global [%0], [%1], 16;" \
                 :: "r"(saddr), "l"(gptr) : "memory")
#define CP_COMMIT() asm volatile("cp.async.commit_group;" ::: "memory")
#define CP_WAIT1()  asm volatile("cp.async.wait_group 1;" ::: "memory")
#define CP_WAIT0()  asm volatile("cp.async.wait_group 0;" ::: "memory")

// ---------------------------------------------------------------------------
// transpose h (B,C,H,W)->(N,C): fp32 + fp16 copies
__global__ void prep_h_kernel(const float* __restrict__ h) {
    __shared__ float tile[32][33];
    int b = blockIdx.z, ct = blockIdx.y, st = blockIdx.x;
    int c0 = ct * 32, s0 = st * 32;
    int tx = threadIdx.x, ty = threadIdx.y;

    const float* src = h + ((size_t)b * C_DIM + c0) * 1024 + s0;
    #pragma unroll
    for (int i = 0; i < 32; i += 8)
        tile[ty + i][tx] = src[(size_t)(ty + i) * 1024 + tx];
    __syncthreads();
    size_t rowbase = (size_t)b * 1024 + s0;
    #pragma unroll
    for (int i = 0; i < 32; i += 8) {
        float x = tile[tx][ty + i];
        size_t idx = (rowbase + ty + i) * C_DIM + c0 + tx;
        g_hflat[idx] = x;
        g_A16[idx]   = __float2half_rn(x);
    }
}

// embedding: fp16 copy + exact 0.5||e||^2 + ||e||
__global__ void prep_emb_kernel(const float* __restrict__ emb) {
    int v = blockIdx.x, t = threadIdx.x;
    float x = emb[v * C_DIM + t];
    g_B16[v * C_DIM + t] = __float2half_rn(x);

    float s = x * x;
    __shared__ float sm[8];
    #pragma unroll
    for (int o = 16; o > 0; o >>= 1) s += __shfl_down_sync(0xFFFFFFFFu, s, o);
    if ((t & 31) == 0) sm[t >> 5] = s;
    __syncthreads();
    if (t == 0) {
        float tot = 0.f;
        #pragma unroll
        for (int i = 0; i < 8; i++) tot += sm[i];
        g_halfnorm[v] = 0.5f * tot;
        g_enorm[v]    = sqrtf(tot);
    }
}

// ||x|| per row (warp per row)
__global__ void xnorm_kernel() {
    int w = threadIdx.x >> 5, lane = threadIdx.x & 31;
    int r = blockIdx.x * 8 + w;
    const float* xr = g_hflat + (size_t)r * C_DIM;
    float p = 0.f;
    #pragma unroll
    for (int i = 0; i < 8; i++) { float x = xr[lane + i * 32]; p = fmaf(x, x, p); }
    #pragma unroll
    for (int o = 16; o > 0; o >>= 1) p += __shfl_xor_sync(0xFFFFFFFFu, p, o);
    if (lane == 0) g_xnorm[r] = sqrtf(p);
}

// deterministic sum(h^2) partials (for loss)
__global__ void sumsq_kernel(const float* __restrict__ h) {
    int t = threadIdx.x;
    size_t base = (size_t)blockIdx.x * 1024;
    float s = 0.f;
    #pragma unroll
    for (int i = t; i < 1024; i += 256) { float x = h[base + i]; s += x * x; }
    __shared__ float sm[8];
    #pragma unroll
    for (int o = 16; o > 0; o >>= 1) s += __shfl_down_sync(0xFFFFFFFFu, s, o);
    if ((t & 31) == 0) sm[t >> 5] = s;
    __syncthreads();
    if (t == 0) {
        float tot = 0.f;
        #pragma unroll
        for (int i = 0; i < 8; i++) tot += sm[i];
        g_partial[blockIdx.x] = tot;
    }
}

// ---------------------------------------------------------------------------
// Pass 1: fp16 WMMA GEMM (A resident), approx scores + maxlower.
// 128 CTAs x 256 threads (8 warps, 4x2 over 128x128 tile).
#define LDA   264               // 256 + 8 halfs
#define LDB   72                // 64 + 8 halfs
#define LDC   132               // 128 + 4 floats
#define OFF_A 0                                 // 128*264*2 = 67584
#define OFF_B 67584                             // 2 stages * 128*72*2 = 36864
#define OFF_C 104448                            // 128*132*4 = 67584
#define OFF_ML 172032                           // 128 floats
#define SMEM_P1 172544

__global__ __launch_bounds__(256, 1) void pass1_kernel() {
    extern __shared__ char smem[];
    const uint32_t sb = smem_u32(smem);
    __half* As = reinterpret_cast<__half*>(smem + OFF_A);
    float*  Cs = reinterpret_cast<float*>(smem + OFF_C);
    float*  ML = reinterpret_cast<float*>(smem + OFF_ML);

    const int tid = threadIdx.x;
    const int w = tid >> 5, lane = tid & 31;
    const int wm = w & 3, wn = w >> 2;
    const int m0 = blockIdx.x * 128;

    if (tid < 128) ML[tid] = -FLT_MAX;

    // load resident A tile: 128 rows x 512B
    {
        #pragma unroll
        for (int i = 0; i < 16; i++) {
            int f = tid + i * 256;
            int r = f >> 5, q = f & 31;
            CP_ASYNC16(sb + OFF_A + (uint32_t)(r * LDA * 2 + q * 16),
                       g_A16 + (size_t)(m0 + r) * C_DIM + q * 8);
        }
        CP_COMMIT();
    }
    // B chunk 0 (vt=0, ck=0) into stage 0
    {
        #pragma unroll
        for (int i = 0; i < 4; i++) {
            int f = tid + i * 256;
            int r = f >> 3, q = f & 7;
            CP_ASYNC16(sb + OFF_B + (uint32_t)(r * LDB * 2 + q * 16),
                       g_B16 + (size_t)r * C_DIM + q * 8);
        }
        CP_COMMIT();
    }
    __syncthreads();

    wmma::fragment<wmma::accumulator, 16, 16, 16, float> acc[2][4];

    for (int gc = 0; gc < 128; gc++) {
        const int ck = gc & 3;
        const int st = gc & 1;
        const int v0 = (gc >> 2) << 7;

        // issue next chunk into the other stage
        if (gc < 127) {
            const int ng = gc + 1;
            const int nv0 = (ng >> 2) << 7;
            const int nck = ng & 3;
            const uint32_t dstb = sb + OFF_B + (uint32_t)((ng & 1) * 18432);
            #pragma unroll
            for (int i = 0; i < 4; i++) {
                int f = tid + i * 256;
                int r = f >> 3, q = f & 7;
                CP_ASYNC16(dstb + (uint32_t)(r * LDB * 2 + q * 16),
                           g_B16 + (size_t)(nv0 + r) * C_DIM + nck * 64 + q * 8);
            }
            CP_COMMIT();
            CP_WAIT1();
        } else {
            CP_WAIT0();
        }
        __syncthreads();

        if (ck == 0) {
            #pragma unroll
            for (int i = 0; i < 2; i++)
                #pragma unroll
                for (int j = 0; j < 4; j++)
                    wmma::fill_fragment(acc[i][j], 0.f);
        }

        const __half* Bs = reinterpret_cast<const __half*>(smem + OFF_B + st * 18432);
        #pragma unroll
        for (int ks = 0; ks < 4; ks++) {
            wmma::fragment<wmma::matrix_a, 16, 16, 16, __half, wmma::row_major> af[2];
            wmma::fragment<wmma::matrix_b, 16, 16, 16, __half, wmma::col_major> bf[4];
            const int kk = ck * 64 + ks * 16;
            #pragma unroll
            for (int i = 0; i < 2; i++)
                wmma::load_matrix_sync(af[i], As + (wm * 32 + i * 16) * LDA + kk, LDA);
            #pragma unroll
            for (int j = 0; j < 4; j++)
                wmma::load_matrix_sync(bf[j], Bs + (wn * 64 + j * 16) * LDB + ks * 16, LDB);
            #pragma unroll
            for (int i = 0; i < 2; i++)
                #pragma unroll
                for (int j = 0; j < 4; j++)
                    wmma::mma_sync(acc[i][j], af[i], bf[j], acc[i][j]);
        }

        if (ck == 3) {
            // epilogue for v-tile [v0, v0+128)
            #pragma unroll
            for (int i = 0; i < 2; i++)
                #pragma unroll
                for (int j = 0; j < 4; j++)
                    wmma::store_matrix_sync(Cs + (wm * 32 + i * 16) * LDC + wn * 64 + j * 16,
                                            acc[i][j], LDC, wmma::mem_row_major);
            __syncthreads();

            #pragma unroll 4
            for (int rr = 0; rr < 16; rr++) {
                const int row = rr * 8 + w;
                const float xn = __ldg(&g_xnorm[m0 + row]);
                float4 c4  = *reinterpret_cast<const float4*>(Cs + row * LDC + lane * 4);
                float4 hn4 = *reinterpret_cast<const float4*>(g_halfnorm + v0 + lane * 4);
                float4 en4 = *reinterpret_cast<const float4*>(g_enorm + v0 + lane * 4);
                float s0 = c4.x - hn4.x, s1 = c4.y - hn4.y;
                float s2 = c4.z - hn4.z, s3 = c4.w - hn4.w;

                __half2 h01 = __floats2half2_rn(s0, s1);
                __half2 h23 = __floats2half2_rn(s2, s3);
                uint2 pk = { *reinterpret_cast<uint32_t*>(&h01),
                             *reinterpret_cast<uint32_t*>(&h23) };
                *reinterpret_cast<uint2*>(g_S16 + (size_t)(m0 + row) * VOCAB + v0 + lane * 4) = pk;

                const float mx = MCOEF * xn;
                float ml = fmaxf(fmaxf(s0 - mx * en4.x, s1 - mx * en4.y),
                                 fmaxf(s2 - mx * en4.z, s3 - mx * en4.w)) - ACC_SLACK;
                #pragma unroll
                for (int o = 16; o > 0; o >>= 1)
                    ml = fmaxf(ml, __shfl_xor_sync(0xFFFFFFFFu, ml, o));
                if (lane == 0) ML[row] = fmaxf(ML[row], ml);
            }
        }
        __syncthreads();
    }

    if (tid < 128) g_maxlower[m0 + tid] = ML[tid];
}

// ---------------------------------------------------------------------------
// Pass 2: candidate scan + exact fp32 rescore. One warp per row.
#define CAP 128
__global__ __launch_bounds__(256) void pass2_kernel(const float* __restrict__ emb) {
    __shared__ unsigned short lists[8][CAP];
    __shared__ int cnts[8];
    const int w = threadIdx.x >> 5, lane = threadIdx.x & 31;
    const int r = blockIdx.x * 8 + w;
    if (lane == 0) cnts[w] = 0;
    __syncwarp();

    const float xn = __ldg(&g_xnorm[r]);
    const float ml = __ldg(&g_maxlower[r]);
    const float mx = MCOEF * xn;
    const __half* srow = g_S16 + (size_t)r * VOCAB;

    #pragma unroll 4
    for (int i = 0; i < 64; i++) {
        const int c = lane * 2 + i * 64;
        __half2 s2 = *reinterpret_cast<const __half2*>(srow + c);
        float2 sf = __half22float2(s2);
        float2 en2 = *reinterpret_cast<const float2*>(g_enorm + c);
        if (sf.x + mx * en2.x + TSLK >= ml) {
            int p = atomicAdd(&cnts[w], 1);
            if (p < CAP) lists[w][p] = (unsigned short)c;
        }
        if (sf.y + mx * en2.y + TSLK >= ml) {
            int p = atomicAdd(&cnts[w], 1);
            if (p < CAP) lists[w][p] = (unsigned short)(c + 1);
        }
    }
    __syncwarp();

    // x row, interleaved across lanes
    float xr[8];
    const float* xp = g_hflat + (size_t)r * C_DIM;
    #pragma unroll
    for (int i = 0; i < 8; i++) xr[i] = xp[lane + i * 32];

    const int n = cnts[w];
    const bool ovf = (n > CAP) || (n == 0);
    const int total = ovf ? VOCAB : n;

    float best = -FLT_MAX;
    int bidx = VOCAB;
    for (int j = 0; j < total; j++) {
        const int v = ovf ? j : (int)lists[w][j];
        const float* ev = emb + (size_t)v * C_DIM;
        float p = 0.f;
        #pragma unroll
        for (int i = 0; i < 8; i++) p = fmaf(xr[i], __ldg(&ev[lane + i * 32]), p);
        #pragma unroll
        for (int o = 16; o > 0; o >>= 1) p += __shfl_xor_sync(0xFFFFFFFFu, p, o);
        const float s = p - __ldg(&g_halfnorm[v]);
        if (s > best || (s == best && v < bidx)) { best = s; bidx = v; }
    }
    if (lane == 0) { g_bestscore[r] = best; g_bestidx[r] = bidx; }
}

// ---------------------------------------------------------------------------
__global__ void gather_kernel(const float* __restrict__ emb, float* __restrict__ out) {
    int bc = blockIdx.x;
    int b = bc >> 8, c = bc & 255;
    int t = threadIdx.x;
    #pragma unroll
    for (int u = 0; u < 4; u++) {
        int sp = t + u * 256;
        int n = b * 1024 + sp;
        out[(size_t)bc * 1024 + sp] = __ldg(&emb[(size_t)g_bestidx[n] * C_DIM + c]);
    }
}

__global__ void indices_kernel(float* __restrict__ out) {
    int n = blockIdx.x * 256 + threadIdx.x;
    out[4194304 + n] = (float)g_bestidx[n];
}

__global__ void loss_kernel(float* __restrict__ out) {
    __shared__ float sm[256];
    int t = threadIdx.x;
    float s1 = 0.f, s2 = 0.f;
    for (int i = t; i < 4096; i += 256)  s1 += g_partial[i];
    for (int i = t; i < N_VEC; i += 256) s2 += g_bestscore[i];
    sm[t] = s1 - 2.f * s2;
    __syncthreads();
    #pragma unroll
    for (int o = 128; o > 0; o >>= 1) {
        if (t < o) sm[t] += sm[t + o];
        __syncthreads();
    }
    if (t == 0) out[4210688] = sm[0] / 4194304.f;
}

// ---------------------------------------------------------------------------
extern "C" void kernel_launch(void* const* d_in, const int* in_sizes, int n_in,
                              void* d_out, int out_size) {
    const float* h   = (const float*)d_in[0];
    const float* emb = (const float*)d_in[1];
    float* out = (float*)d_out;

    static bool attr_set = false;
    if (!attr_set) {
        cudaFuncSetAttribute(pass1_kernel,
                             cudaFuncAttributeMaxDynamicSharedMemorySize, SMEM_P1);
        attr_set = true;
    }

    dim3 tgrid(32, 8, 16), tblk(32, 8);
    prep_h_kernel<<<tgrid, tblk>>>(h);
    prep_emb_kernel<<<VOCAB, 256>>>(emb);
    xnorm_kernel<<<N_VEC / 8, 256>>>();
    sumsq_kernel<<<4096, 256>>>(h);

    pass1_kernel<<<128, 256, SMEM_P1>>>();
    pass2_kernel<<<N_VEC / 8, 256>>>(emb);

    gather_kernel<<<4096, 256>>>(emb, out);
    indices_kernel<<<N_VEC / 256, 256>>>(out);
    loss_kernel<<<1, 256>>>(out);
}

// round 5
// speedup vs baseline: 5.2288x; 1.0085x over previous
#include <cuda_runtime.h>
#include <cuda_fp16.h>
#include <mma.h>
#include <cstdint>
#include <cfloat>

using namespace nvcuda;

#define N_VEC  16384
#define VOCAB  4096
#define C_DIM  256

// rigorous fp16-quantization margin: |s_hat - s_exact| <= MCOEF*||x||*||e|| + SLK
#define MCOEF  1.06e-3f
#define SLK    0.05f

// ---------------------------------------------------------------------------
// device-global scratch (no allocations allowed)
__device__ float  g_hflat[N_VEC * C_DIM];     // h transposed (N,C) fp32
__device__ __half g_A16[N_VEC * C_DIM];       // fp16 copy
__device__ __half g_B16[VOCAB * C_DIM];       // fp16 codebook
__device__ float  g_halfnorm[VOCAB];          // 0.5*||e||^2 exact
__device__ float  g_enorm[VOCAB];             // ||e||
__device__ float  g_xnorm[N_VEC];             // ||x||
__device__ float  g_bestscore[N_VEC];
__device__ int    g_bestidx[N_VEC];
__device__ float  g_partial[4096];

// ---------------------------------------------------------------------------
__device__ __forceinline__ uint32_t smem_u32(const void* p) {
    uint32_t a;
    asm("{ .reg .u64 t; cvta.to.shared.u64 t, %1; cvt.u32.u64 %0, t; }"
        : "=r"(a) : "l"(p));
    return a;
}
#define CP_ASYNC16(saddr, gptr) \
    asm volatile("cp.async.cg.shared.global [%0], [%1], 16;" \
                 :: "r"(saddr), "l"(gptr) : "memory")
#define CP_COMMIT() asm volatile("cp.async.commit_group;" ::: "memory")
#define CP_WAIT1()  asm volatile("cp.async.wait_group 1;" ::: "memory")
#define CP_WAIT0()  asm volatile("cp.async.wait_group 0;" ::: "memory")

// ---------------------------------------------------------------------------
// transpose h (B,C,H,W)->(N,C): fp32 + fp16 copies, fused sum(h^2) partial
__global__ void prep_h_kernel(const float* __restrict__ h) {
    __shared__ float tile[32][33];
    __shared__ float rsm[8];
    int b = blockIdx.z, ct = blockIdx.y, st = blockIdx.x;
    int c0 = ct * 32, s0 = st * 32;
    int tx = threadIdx.x, ty = threadIdx.y;
    int t = ty * 32 + tx;

    const float* src = h + ((size_t)b * C_DIM + c0) * 1024 + s0;
    float sq = 0.f;
    #pragma unroll
    for (int i = 0; i < 32; i += 8) {
        float v = src[(size_t)(ty + i) * 1024 + tx];
        tile[ty + i][tx] = v;
        sq = fmaf(v, v, sq);
    }
    __syncthreads();
    size_t rowbase = (size_t)b * 1024 + s0;
    #pragma unroll
    for (int i = 0; i < 32; i += 8) {
        float x = tile[tx][ty + i];
        size_t idx = (rowbase + ty + i) * C_DIM + c0 + tx;
        g_hflat[idx] = x;
        g_A16[idx]   = __float2half_rn(x);
    }
    // deterministic block partial of sum(h^2)
    #pragma unroll
    for (int o = 16; o > 0; o >>= 1) sq += __shfl_down_sync(0xFFFFFFFFu, sq, o);
    if ((t & 31) == 0) rsm[t >> 5] = sq;
    __syncthreads();
    if (t == 0) {
        float tot = 0.f;
        #pragma unroll
        for (int i = 0; i < 8; i++) tot += rsm[i];
        g_partial[(b * 8 + ct) * 32 + st] = tot;
    }
}

// embedding: fp16 copy + exact 0.5||e||^2 + ||e||
__global__ void prep_emb_kernel(const float* __restrict__ emb) {
    int v = blockIdx.x, t = threadIdx.x;
    float x = emb[v * C_DIM + t];
    g_B16[v * C_DIM + t] = __float2half_rn(x);

    float s = x * x;
    __shared__ float sm[8];
    #pragma unroll
    for (int o = 16; o > 0; o >>= 1) s += __shfl_down_sync(0xFFFFFFFFu, s, o);
    if ((t & 31) == 0) sm[t >> 5] = s;
    __syncthreads();
    if (t == 0) {
        float tot = 0.f;
        #pragma unroll
        for (int i = 0; i < 8; i++) tot += sm[i];
        g_halfnorm[v] = 0.5f * tot;
        g_enorm[v]    = sqrtf(tot);
    }
}

// ||x|| per row (warp per row)
__global__ void xnorm_kernel() {
    int w = threadIdx.x >> 5, lane = threadIdx.x & 31;
    int r = blockIdx.x * 8 + w;
    const float* xr = g_hflat + (size_t)r * C_DIM;
    float p = 0.f;
    #pragma unroll
    for (int i = 0; i < 8; i++) { float x = xr[lane + i * 32]; p = fmaf(x, x, p); }
    #pragma unroll
    for (int o = 16; o > 0; o >>= 1) p += __shfl_xor_sync(0xFFFFFFFFu, p, o);
    if (lane == 0) g_xnorm[r] = sqrtf(p);
}

// ---------------------------------------------------------------------------
// Fused: fp16 WMMA GEMM + running-maxlower candidate filter + exact rescore.
// 128 CTAs x 256 threads (8 warps, 4x2 over the 128x128 tile).
#define LDA   264               // halfs (256 + 8)
#define LDB   136               // halfs (128 + 8)
#define LDC   132               // floats (128 + 4)
#define CAP   64
#define OFF_A    0               // 128*264*2            = 67584
#define OFF_B    67584           // 2 stages * 128*136*2 = 69632
#define OFF_C    137216          // 128*132*4            = 67584
#define OFF_ML   204800          // 128 floats
#define OFF_CNT  205312          // 128 ints
#define OFF_CAND 205824          // 128*64 u16           = 16384
#define SMEM_P1  222208

__global__ __launch_bounds__(256, 1) void pass1_kernel(const float* __restrict__ emb) {
    extern __shared__ char smem[];
    const uint32_t sb = smem_u32(smem);
    __half* As = reinterpret_cast<__half*>(smem + OFF_A);
    float*  Cs = reinterpret_cast<float*>(smem + OFF_C);
    float*  ML = reinterpret_cast<float*>(smem + OFF_ML);
    int*    CNT = reinterpret_cast<int*>(smem + OFF_CNT);
    unsigned short* CAND = reinterpret_cast<unsigned short*>(smem + OFF_CAND);

    const int tid = threadIdx.x;
    const int w = tid >> 5, lane = tid & 31;
    const int wm = w & 3, wn = w >> 2;
    const int m0 = blockIdx.x * 128;

    if (tid < 128) { ML[tid] = -FLT_MAX; CNT[tid] = 0; }

    // resident A tile: 128 rows x 512B
    #pragma unroll
    for (int i = 0; i < 16; i++) {
        int f = tid + i * 256;
        int r = f >> 5, q = f & 31;
        CP_ASYNC16(sb + OFF_A + (uint32_t)(r * LDA * 2 + q * 16),
                   g_A16 + (size_t)(m0 + r) * C_DIM + q * 8);
    }
    CP_COMMIT();
    // B chunk 0 into stage 0 (128 rows x 256B)
    #pragma unroll
    for (int i = 0; i < 8; i++) {
        int f = tid + i * 256;
        int r = f >> 4, q = f & 15;
        CP_ASYNC16(sb + OFF_B + (uint32_t)(r * LDB * 2 + q * 16),
                   g_B16 + (size_t)r * C_DIM + q * 8);
    }
    CP_COMMIT();

    wmma::fragment<wmma::accumulator, 16, 16, 16, float> acc[2][4];

    for (int gc = 0; gc < 64; gc++) {
        const int kc = gc & 1;          // K chunk within v-tile (0: k<128, 1: k>=128)
        const int v0 = (gc >> 1) << 7;

        // prefetch next chunk into the other stage
        if (gc < 63) {
            const int ng = gc + 1;
            const int nv0 = (ng >> 1) << 7;
            const int nk0 = (ng & 1) * 128;
            const uint32_t dstb = sb + OFF_B + (uint32_t)((ng & 1) * (128 * LDB * 2));
            #pragma unroll
            for (int i = 0; i < 8; i++) {
                int f = tid + i * 256;
                int r = f >> 4, q = f & 15;
                CP_ASYNC16(dstb + (uint32_t)(r * LDB * 2 + q * 16),
                           g_B16 + (size_t)(nv0 + r) * C_DIM + nk0 + q * 8);
            }
            CP_COMMIT();
            CP_WAIT1();
        } else {
            CP_WAIT0();
        }
        __syncthreads();

        if (kc == 0) {
            #pragma unroll
            for (int i = 0; i < 2; i++)
                #pragma unroll
                for (int j = 0; j < 4; j++)
                    wmma::fill_fragment(acc[i][j], 0.f);
        }

        const __half* Bs = reinterpret_cast<const __half*>(
            smem + OFF_B + (gc & 1) * (128 * LDB * 2));
        #pragma unroll
        for (int ks = 0; ks < 8; ks++) {
            wmma::fragment<wmma::matrix_a, 16, 16, 16, __half, wmma::row_major> af[2];
            wmma::fragment<wmma::matrix_b, 16, 16, 16, __half, wmma::col_major> bf[4];
            const int ka = kc * 128 + ks * 16;
            #pragma unroll
            for (int i = 0; i < 2; i++)
                wmma::load_matrix_sync(af[i], As + (wm * 32 + i * 16) * LDA + ka, LDA);
            #pragma unroll
            for (int j = 0; j < 4; j++)
                wmma::load_matrix_sync(bf[j], Bs + (wn * 64 + j * 16) * LDB + ks * 16, LDB);
            #pragma unroll
            for (int i = 0; i < 2; i++)
                #pragma unroll
                for (int j = 0; j < 4; j++)
                    wmma::mma_sync(acc[i][j], af[i], bf[j], acc[i][j]);
        }

        if (kc == 1) {
            // ---- epilogue for v-tile [v0, v0+128) ----
            #pragma unroll
            for (int i = 0; i < 2; i++)
                #pragma unroll
                for (int j = 0; j < 4; j++)
                    wmma::store_matrix_sync(Cs + (wm * 32 + i * 16) * LDC + wn * 64 + j * 16,
                                            acc[i][j], LDC, wmma::mem_row_major);
            __syncthreads();

            // warp w owns rows {w, w+8, ...}; lanes cover 128 cols (4 each)
            #pragma unroll 2
            for (int rr = 0; rr < 16; rr++) {
                const int row = rr * 8 + w;
                const float mx = MCOEF * __ldg(&g_xnorm[m0 + row]);
                float4 c4  = *reinterpret_cast<const float4*>(Cs + row * LDC + lane * 4);
                float4 hn4 = *reinterpret_cast<const float4*>(g_halfnorm + v0 + lane * 4);
                float4 en4 = *reinterpret_cast<const float4*>(g_enorm + v0 + lane * 4);
                float s0 = c4.x - hn4.x, s1 = c4.y - hn4.y;
                float s2 = c4.z - hn4.z, s3 = c4.w - hn4.w;
                float m0e = mx * en4.x + SLK, m1e = mx * en4.y + SLK;
                float m2e = mx * en4.z + SLK, m3e = mx * en4.w + SLK;

                // raise running max-lower for this row
                float ml = fmaxf(fmaxf(s0 - m0e, s1 - m1e), fmaxf(s2 - m2e, s3 - m3e));
                #pragma unroll
                for (int o = 16; o > 0; o >>= 1)
                    ml = fmaxf(ml, __shfl_xor_sync(0xFFFFFFFFu, ml, o));
                if (lane == 0) ML[row] = fmaxf(ML[row], ml);
                __syncwarp();
                const float thr = ML[row];

                // push survivors: upper bound >= running max-lower
                const int vb = v0 + lane * 4;
                if (s0 + m0e >= thr) {
                    int p = atomicAdd(&CNT[row], 1);
                    if (p < CAP) CAND[row * CAP + p] = (unsigned short)(vb + 0);
                }
                if (s1 + m1e >= thr) {
                    int p = atomicAdd(&CNT[row], 1);
                    if (p < CAP) CAND[row * CAP + p] = (unsigned short)(vb + 1);
                }
                if (s2 + m2e >= thr) {
                    int p = atomicAdd(&CNT[row], 1);
                    if (p < CAP) CAND[row * CAP + p] = (unsigned short)(vb + 2);
                }
                if (s3 + m3e >= thr) {
                    int p = atomicAdd(&CNT[row], 1);
                    if (p < CAP) CAND[row * CAP + p] = (unsigned short)(vb + 3);
                }
            }
        }
        __syncthreads();
    }

    // ---- exact fp32 rescore of candidates (same CTA) ----
    for (int rr = 0; rr < 16; rr++) {
        const int row = rr * 8 + w;
        const int r = m0 + row;
        float xr[8];
        const float* xp = g_hflat + (size_t)r * C_DIM;
        #pragma unroll
        for (int i = 0; i < 8; i++) xr[i] = xp[lane + i * 32];

        const int n = CNT[row];
        const bool full = (n > CAP);
        const int total = full ? VOCAB : n;

        float best = -FLT_MAX;
        int bidx = VOCAB;
        for (int j = 0; j < total; j++) {
            const int v = full ? j : (int)CAND[row * CAP + j];
            const float* ev = emb + (size_t)v * C_DIM;
            float p = 0.f;
            #pragma unroll
            for (int i = 0; i < 8; i++) p = fmaf(xr[i], __ldg(&ev[lane + i * 32]), p);
            #pragma unroll
            for (int o = 16; o > 0; o >>= 1) p += __shfl_xor_sync(0xFFFFFFFFu, p, o);
            const float s = p - __ldg(&g_halfnorm[v]);
            if (s > best || (s == best && v < bidx)) { best = s; bidx = v; }
        }
        if (lane == 0) { g_bestscore[r] = best; g_bestidx[r] = bidx; }
    }
}

// ---------------------------------------------------------------------------
__global__ void gather_kernel(const float* __restrict__ emb, float* __restrict__ out) {
    int bc = blockIdx.x;
    int b = bc >> 8, c = bc & 255;
    int t = threadIdx.x;
    #pragma unroll
    for (int u = 0; u < 4; u++) {
        int sp = t + u * 256;
        int n = b * 1024 + sp;
        out[(size_t)bc * 1024 + sp] = __ldg(&emb[(size_t)g_bestidx[n] * C_DIM + c]);
    }
}

__global__ void indices_kernel(float* __restrict__ out) {
    int n = blockIdx.x * 256 + threadIdx.x;
    out[4194304 + n] = (float)g_bestidx[n];
}

__global__ void loss_kernel(float* __restrict__ out) {
    __shared__ float sm[256];
    int t = threadIdx.x;
    float s1 = 0.f, s2 = 0.f;
    for (int i = t; i < 4096; i += 256)  s1 += g_partial[i];
    for (int i = t; i < N_VEC; i += 256) s2 += g_bestscore[i];
    sm[t] = s1 - 2.f * s2;
    __syncthreads();
    #pragma unroll
    for (int o = 128; o > 0; o >>= 1) {
        if (t < o) sm[t] += sm[t + o];
        __syncthreads();
    }
    if (t == 0) out[4210688] = sm[0] / 4194304.f;
}

// ---------------------------------------------------------------------------
extern "C" void kernel_launch(void* const* d_in, const int* in_sizes, int n_in,
                              void* d_out, int out_size) {
    const float* h   = (const float*)d_in[0];
    const float* emb = (const float*)d_in[1];
    float* out = (float*)d_out;

    static bool attr_set = false;
    if (!attr_set) {
        cudaFuncSetAttribute(pass1_kernel,
                             cudaFuncAttributeMaxDynamicSharedMemorySize, SMEM_P1);
        attr_set = true;
    }

    dim3 tgrid(32, 8, 16), tblk(32, 8);
    prep_h_kernel<<<tgrid, tblk>>>(h);
    prep_emb_kernel<<<VOCAB, 256>>>(emb);
    xnorm_kernel<<<N_VEC / 8, 256>>>();

    pass1_kernel<<<128, 256, SMEM_P1>>>(emb);

    gather_kernel<<<4096, 256>>>(emb, out);
    indices_kernel<<<N_VEC / 256, 256>>>(out);
    loss_kernel<<<1, 256>>>(out);
}

// round 7
// speedup vs baseline: 7.0219x; 1.3429x over previous
#include <cuda_runtime.h>
#include <cuda_fp16.h>
#include <cstdint>
#include <cfloat>

#define N_VEC  16384
#define VOCAB  4096
#define C_DIM  256

// rigorous fp16-quantization margin: |s_hat - s_exact| <= MCOEF*||x||*||e|| + SLK
#define MCOEF  1.06e-3f
#define SLK    0.05f

// ---------------------------------------------------------------------------
__device__ float  g_hflat[N_VEC * C_DIM];     // h transposed (N,C) fp32
__device__ __half g_A16[N_VEC * C_DIM];       // fp16 copy
__device__ __half g_B16[VOCAB * C_DIM];       // fp16 codebook
__device__ float  g_halfnorm[VOCAB];          // 0.5*||e||^2 exact
__device__ float  g_enorm[VOCAB];             // ||e||
__device__ float  g_xnorm[N_VEC];             // ||x||
__device__ float  g_bestscore[N_VEC];
__device__ int    g_bestidx[N_VEC];
__device__ float  g_partial[4096];

// ---------------------------------------------------------------------------
__device__ __forceinline__ uint32_t smem_u32(const void* p) {
    uint32_t a;
    asm("{ .reg .u64 t; cvta.to.shared.u64 t, %1; cvt.u32.u64 %0, t; }"
        : "=r"(a) : "l"(p));
    return a;
}
__device__ __forceinline__ unsigned fmap(float f) {
    unsigned u = __float_as_uint(f);
    return u ^ ((unsigned)((int)u >> 31) | 0x80000000u);
}
#define CP_ASYNC16(saddr, gptr) \
    asm volatile("cp.async.cg.shared.global [%0], [%1], 16;" \
                 :: "r"(saddr), "l"(gptr) : "memory")
#define CP_COMMIT() asm volatile("cp.async.commit_group;" ::: "memory")
#define CP_WAIT1()  asm volatile("cp.async.wait_group 1;" ::: "memory")
#define CP_WAIT0()  asm volatile("cp.async.wait_group 0;" ::: "memory")

#define MMA16816(c, a, b) \
    asm volatile( \
        "mma.sync.aligned.m16n8k16.row.col.f32.f16.f16.f32 " \
        "{%0,%1,%2,%3}, {%4,%5,%6,%7}, {%8,%9}, {%0,%1,%2,%3};" \
        : "+f"((c)[0]), "+f"((c)[1]), "+f"((c)[2]), "+f"((c)[3]) \
        : "r"((a)[0]), "r"((a)[1]), "r"((a)[2]), "r"((a)[3]), \
          "r"((b)[0]), "r"((b)[1]))

// ---------------------------------------------------------------------------
// transpose h (B,C,H,W)->(N,C): fp32 + fp16 copies, fused sum(h^2) partial
__global__ void prep_h_kernel(const float* __restrict__ h) {
    __shared__ float tile[32][33];
    __shared__ float rsm[8];
    int b = blockIdx.z, ct = blockIdx.y, st = blockIdx.x;
    int c0 = ct * 32, s0 = st * 32;
    int tx = threadIdx.x, ty = threadIdx.y;
    int t = ty * 32 + tx;

    const float* src = h + ((size_t)b * C_DIM + c0) * 1024 + s0;
    float sq = 0.f;
    #pragma unroll
    for (int i = 0; i < 32; i += 8) {
        float v = src[(size_t)(ty + i) * 1024 + tx];
        tile[ty + i][tx] = v;
        sq = fmaf(v, v, sq);
    }
    __syncthreads();
    size_t rowbase = (size_t)b * 1024 + s0;
    #pragma unroll
    for (int i = 0; i < 32; i += 8) {
        float x = tile[tx][ty + i];
        size_t idx = (rowbase + ty + i) * C_DIM + c0 + tx;
        g_hflat[idx] = x;
        g_A16[idx]   = __float2half_rn(x);
    }
    #pragma unroll
    for (int o = 16; o > 0; o >>= 1) sq += __shfl_down_sync(0xFFFFFFFFu, sq, o);
    if ((t & 31) == 0) rsm[t >> 5] = sq;
    __syncthreads();
    if (t == 0) {
        float tot = 0.f;
        #pragma unroll
        for (int i = 0; i < 8; i++) tot += rsm[i];
        g_partial[(b * 8 + ct) * 32 + st] = tot;
    }
}

__global__ void prep_emb_kernel(const float* __restrict__ emb) {
    int v = blockIdx.x, t = threadIdx.x;
    float x = emb[v * C_DIM + t];
    g_B16[v * C_DIM + t] = __float2half_rn(x);

    float s = x * x;
    __shared__ float sm[8];
    #pragma unroll
    for (int o = 16; o > 0; o >>= 1) s += __shfl_down_sync(0xFFFFFFFFu, s, o);
    if ((t & 31) == 0) sm[t >> 5] = s;
    __syncthreads();
    if (t == 0) {
        float tot = 0.f;
        #pragma unroll
        for (int i = 0; i < 8; i++) tot += sm[i];
        g_halfnorm[v] = 0.5f * tot;
        g_enorm[v]    = sqrtf(tot);
    }
}

__global__ void xnorm_kernel() {
    int w = threadIdx.x >> 5, lane = threadIdx.x & 31;
    int r = blockIdx.x * 8 + w;
    const float* xr = g_hflat + (size_t)r * C_DIM;
    float p = 0.f;
    #pragma unroll
    for (int i = 0; i < 8; i++) { float x = xr[lane + i * 32]; p = fmaf(x, x, p); }
    #pragma unroll
    for (int o = 16; o > 0; o >>= 1) p += __shfl_xor_sync(0xFFFFFFFFu, p, o);
    if (lane == 0) g_xnorm[r] = sqrtf(p);
}

// ---------------------------------------------------------------------------
// Fused mma.sync GEMM + register epilogue filter + exact rescore.
// 256 CTAs (M tile 64) x 256 threads (8 warps: wm in {0,1} x wn in {0..3}).
// Warp tile 32x32. v-tile N=128, K chunks of 128 (2 per v-tile).
#define MTILE 64
#define LDA   264        // halfs: 256 + 8  (row stride 132 words = +4 banks)
#define LDB   136        // halfs: 128 + 8  (row stride  68 words = +4 banks)
#define CAP   32
#define OFF_A    0                        // 64*264*2   = 33792
#define OFF_B    33792                    // 2*128*136*2= 69632
#define OFF_XN   103424                   // 64 floats
#define OFF_ML   103680                   // 64 u32
#define OFF_CNT  103936                   // 64 ints
#define OFF_CAND 104192                   // 64*32 u16  = 4096
#define SMEM_P1  108288

__global__ __launch_bounds__(256, 2) void pass1_kernel(const float* __restrict__ emb) {
    extern __shared__ char smem[];
    const uint32_t sb = smem_u32(smem);
    float*    XN  = reinterpret_cast<float*>(smem + OFF_XN);
    unsigned* ML  = reinterpret_cast<unsigned*>(smem + OFF_ML);
    int*      CNT = reinterpret_cast<int*>(smem + OFF_CNT);
    unsigned short* CAND = reinterpret_cast<unsigned short*>(smem + OFF_CAND);

    const int tid = threadIdx.x;
    const int w = tid >> 5, lane = tid & 31;
    const int wm = w & 1, wn = w >> 1;
    const int m0 = blockIdx.x * MTILE;
    const int lg = lane >> 2;        // group id 0..7
    const int lq = lane & 3;         // quad id 0..3

    if (tid < 64) {
        XN[tid] = __ldg(&g_xnorm[m0 + tid]);
        ML[tid] = 0u;                 // maps to "below -inf"
        CNT[tid] = 0;
    }

    // resident A tile: 64 rows x 512B
    #pragma unroll
    for (int i = 0; i < 8; i++) {
        int f = tid + i * 256;
        int r = f >> 5, q = f & 31;
        CP_ASYNC16(sb + OFF_A + (uint32_t)(r * LDA * 2 + q * 16),
                   g_A16 + (size_t)(m0 + r) * C_DIM + q * 8);
    }
    CP_COMMIT();
    // B chunk 0 into stage 0 (128 rows x 256B)
    #pragma unroll
    for (int i = 0; i < 8; i++) {
        int f = tid + i * 256;
        int r = f >> 4, q = f & 15;
        CP_ASYNC16(sb + OFF_B + (uint32_t)(r * LDB * 2 + q * 16),
                   g_B16 + (size_t)r * C_DIM + q * 8);
    }
    CP_COMMIT();

    const __half* As = reinterpret_cast<const __half*>(smem + OFF_A);
    float acc[2][4][4];

    for (int gc = 0; gc < 64; gc++) {
        const int kc = gc & 1;
        const int v0 = (gc >> 1) << 7;

        // prefetch next chunk into the other stage.
        // NOTE: end-of-loop __syncthreads() below guarantees no warp is still
        // reading the stage this prefetch overwrites (stage (gc+2)&1 == gc&1
        // was read in iteration gc; barrier separates those reads from these
        // writes issued in iteration gc+1).
        if (gc < 63) {
            const int ng = gc + 1;
            const int nv0 = (ng >> 1) << 7;
            const int nk0 = (ng & 1) * 128;
            const uint32_t dstb = sb + OFF_B + (uint32_t)((ng & 1) * (128 * LDB * 2));
            #pragma unroll
            for (int i = 0; i < 8; i++) {
                int f = tid + i * 256;
                int r = f >> 4, q = f & 15;
                CP_ASYNC16(dstb + (uint32_t)(r * LDB * 2 + q * 16),
                           g_B16 + (size_t)(nv0 + r) * C_DIM + nk0 + q * 8);
            }
            CP_COMMIT();
            CP_WAIT1();
        } else {
            CP_WAIT0();
        }
        __syncthreads();

        if (kc == 0) {
            #pragma unroll
            for (int mf = 0; mf < 2; mf++)
                #pragma unroll
                for (int nf = 0; nf < 4; nf++)
                    #pragma unroll
                    for (int i = 0; i < 4; i++) acc[mf][nf][i] = 0.f;
        }

        const __half* Bs = reinterpret_cast<const __half*>(
            smem + OFF_B + (gc & 1) * (128 * LDB * 2));

        #pragma unroll
        for (int ks = 0; ks < 8; ks++) {
            const int ka = kc * 128 + ks * 16 + lq * 2;
            uint32_t a[2][4], b[4][2];
            #pragma unroll
            for (int mf = 0; mf < 2; mf++) {
                const __half* ap = As + (wm * 32 + mf * 16 + lg) * LDA + ka;
                a[mf][0] = *reinterpret_cast<const uint32_t*>(ap);
                a[mf][1] = *reinterpret_cast<const uint32_t*>(ap + 8 * LDA);
                a[mf][2] = *reinterpret_cast<const uint32_t*>(ap + 8);
                a[mf][3] = *reinterpret_cast<const uint32_t*>(ap + 8 * LDA + 8);
            }
            const int kb = ks * 16 + lq * 2;
            #pragma unroll
            for (int nf = 0; nf < 4; nf++) {
                const __half* bp = Bs + (wn * 32 + nf * 8 + lg) * LDB + kb;
                b[nf][0] = *reinterpret_cast<const uint32_t*>(bp);
                b[nf][1] = *reinterpret_cast<const uint32_t*>(bp + 8);
            }
            #pragma unroll
            for (int mf = 0; mf < 2; mf++)
                #pragma unroll
                for (int nf = 0; nf < 4; nf++)
                    MMA16816(acc[mf][nf], a[mf], b[nf]);
        }

        if (kc == 1) {
            // ---- register epilogue for v-tile [v0, v0+128) ----
            // acc[mf][nf] rows: wm*32+mf*16+lg (+8); cols: wn*32+nf*8+lq*2 (+1)
            const int rbase = wm * 32 + lg;
            // phase 1: bias, bounds, running max-lower; overwrite acc with UB
            #pragma unroll
            for (int mf = 0; mf < 2; mf++) {
                #pragma unroll
                for (int hh = 0; hh < 2; hh++) {
                    const int row = rbase + mf * 16 + hh * 8;
                    const float mx = MCOEF * XN[row];
                    float lowmax = -FLT_MAX;
                    #pragma unroll
                    for (int nf = 0; nf < 4; nf++) {
                        const int col = wn * 32 + nf * 8 + lq * 2;
                        float2 hn2 = *reinterpret_cast<const float2*>(g_halfnorm + v0 + col);
                        float2 en2 = *reinterpret_cast<const float2*>(g_enorm + v0 + col);
                        float s0 = acc[mf][nf][2 * hh]     - hn2.x;
                        float s1 = acc[mf][nf][2 * hh + 1] - hn2.y;
                        float me0 = fmaf(mx, en2.x, SLK);
                        float me1 = fmaf(mx, en2.y, SLK);
                        lowmax = fmaxf(lowmax, fmaxf(s0 - me0, s1 - me1));
                        acc[mf][nf][2 * hh]     = s0 + me0;   // upper bound
                        acc[mf][nf][2 * hh + 1] = s1 + me1;
                    }
                    atomicMax(&ML[row], fmap(lowmax));
                }
            }
            __syncthreads();
            // phase 2: push survivors
            #pragma unroll
            for (int mf = 0; mf < 2; mf++) {
                #pragma unroll
                for (int hh = 0; hh < 2; hh++) {
                    const int row = rbase + mf * 16 + hh * 8;
                    const unsigned thr = ML[row];
                    #pragma unroll
                    for (int nf = 0; nf < 4; nf++) {
                        const int col = v0 + wn * 32 + nf * 8 + lq * 2;
                        if (fmap(acc[mf][nf][2 * hh]) >= thr) {
                            int p = atomicAdd(&CNT[row], 1);
                            if (p < CAP) CAND[row * CAP + p] = (unsigned short)col;
                        }
                        if (fmap(acc[mf][nf][2 * hh + 1]) >= thr) {
                            int p = atomicAdd(&CNT[row], 1);
                            if (p < CAP) CAND[row * CAP + p] = (unsigned short)(col + 1);
                        }
                    }
                }
            }
        }
        // separate this iteration's B-stage reads (and ML/CNT traffic) from
        // the next iteration's prefetch writes — removing this was the R6 bug
        __syncthreads();
    }

    // ---- exact fp32 rescore of candidates (warp per row) ----
    for (int rr = 0; rr < 8; rr++) {
        const int row = rr * 8 + w;
        const int r = m0 + row;
        float xr[8];
        const float* xp = g_hflat + (size_t)r * C_DIM;
        #pragma unroll
        for (int i = 0; i < 8; i++) xr[i] = xp[lane + i * 32];

        const int n = CNT[row];
        const bool full = (n > CAP);
        const int total = full ? VOCAB : n;

        float best = -FLT_MAX;
        int bidx = VOCAB;
        for (int j = 0; j < total; j++) {
            const int v = full ? j : (int)CAND[row * CAP + j];
            const float* ev = emb + (size_t)v * C_DIM;
            float p = 0.f;
            #pragma unroll
            for (int i = 0; i < 8; i++) p = fmaf(xr[i], __ldg(&ev[lane + i * 32]), p);
            #pragma unroll
            for (int o = 16; o > 0; o >>= 1) p += __shfl_xor_sync(0xFFFFFFFFu, p, o);
            const float s = p - __ldg(&g_halfnorm[v]);
            if (s > best || (s == best && v < bidx)) { best = s; bidx = v; }
        }
        if (lane == 0) { g_bestscore[r] = best; g_bestidx[r] = bidx; }
    }
}

// ---------------------------------------------------------------------------
__global__ void gather_kernel(const float* __restrict__ emb, float* __restrict__ out) {
    int bc = blockIdx.x;
    int b = bc >> 8, c = bc & 255;
    int t = threadIdx.x;
    #pragma unroll
    for (int u = 0; u < 4; u++) {
        int sp = t + u * 256;
        int n = b * 1024 + sp;
        out[(size_t)bc * 1024 + sp] = __ldg(&emb[(size_t)g_bestidx[n] * C_DIM + c]);
    }
}

__global__ void indices_kernel(float* __restrict__ out) {
    int n = blockIdx.x * 256 + threadIdx.x;
    out[4194304 + n] = (float)g_bestidx[n];
}

__global__ void loss_kernel(float* __restrict__ out) {
    __shared__ float sm[256];
    int t = threadIdx.x;
    float s1 = 0.f, s2 = 0.f;
    for (int i = t; i < 4096; i += 256)  s1 += g_partial[i];
    for (int i = t; i < N_VEC; i += 256) s2 += g_bestscore[i];
    sm[t] = s1 - 2.f * s2;
    __syncthreads();
    #pragma unroll
    for (int o = 128; o > 0; o >>= 1) {
        if (t < o) sm[t] += sm[t + o];
        __syncthreads();
    }
    if (t == 0) out[4210688] = sm[0] / 4194304.f;
}

// ---------------------------------------------------------------------------
extern "C" void kernel_launch(void* const* d_in, const int* in_sizes, int n_in,
                              void* d_out, int out_size) {
    const float* h   = (const float*)d_in[0];
    const float* emb = (const float*)d_in[1];
    float* out = (float*)d_out;

    static bool attr_set = false;
    if (!attr_set) {
        cudaFuncSetAttribute(pass1_kernel,
                             cudaFuncAttributeMaxDynamicSharedMemorySize, SMEM_P1);
        attr_set = true;
    }

    dim3 tgrid(32, 8, 16), tblk(32, 8);
    prep_h_kernel<<<tgrid, tblk>>>(h);
    prep_emb_kernel<<<VOCAB, 256>>>(emb);
    xnorm_kernel<<<N_VEC / 8, 256>>>();

    pass1_kernel<<<N_VEC / MTILE, 256, SMEM_P1>>>(emb);

    gather_kernel<<<4096, 256>>>(emb, out);
    indices_kernel<<<N_VEC / 256, 256>>>(out);
    loss_kernel<<<1, 256>>>(out);
}

// round 8
// speedup vs baseline: 7.5861x; 1.0803x over previous
#include <cuda_runtime.h>
#include <cuda_fp16.h>
#include <cstdint>
#include <cfloat>

#define N_VEC  16384
#define VOCAB  4096
#define C_DIM  256

// rigorous fp16-quantization margin: |s_hat - s_exact| <= MCOEF*||x||*||e|| + SLK
#define MCOEF  1.06e-3f
#define SLK    0.05f

// ---------------------------------------------------------------------------
__device__ float  g_hflat[N_VEC * C_DIM];     // h transposed (N,C) fp32
__device__ __half g_A16[N_VEC * C_DIM];       // fp16 copy
__device__ __half g_B16[VOCAB * C_DIM];       // fp16 codebook
__device__ float  g_halfnorm[VOCAB];          // 0.5*||e||^2 exact
__device__ float  g_enorm[VOCAB];             // ||e||
__device__ float  g_xnorm[N_VEC];             // ||x||
__device__ float  g_bestscore[N_VEC];
__device__ int    g_bestidx[N_VEC];
__device__ float  g_partial[4096];

// ---------------------------------------------------------------------------
__device__ __forceinline__ uint32_t smem_u32(const void* p) {
    uint32_t a;
    asm("{ .reg .u64 t; cvta.to.shared.u64 t, %1; cvt.u32.u64 %0, t; }"
        : "=r"(a) : "l"(p));
    return a;
}
__device__ __forceinline__ unsigned fmap(float f) {
    unsigned u = __float_as_uint(f);
    return u ^ ((unsigned)((int)u >> 31) | 0x80000000u);
}
#define CP_ASYNC16(saddr, gptr) \
    asm volatile("cp.async.cg.shared.global [%0], [%1], 16;" \
                 :: "r"(saddr), "l"(gptr) : "memory")
#define CP_COMMIT() asm volatile("cp.async.commit_group;" ::: "memory")
#define CP_WAIT1()  asm volatile("cp.async.wait_group 1;" ::: "memory")
#define CP_WAIT0()  asm volatile("cp.async.wait_group 0;" ::: "memory")

#define MMA16816(c, a, b) \
    asm volatile( \
        "mma.sync.aligned.m16n8k16.row.col.f32.f16.f16.f32 " \
        "{%0,%1,%2,%3}, {%4,%5,%6,%7}, {%8,%9}, {%0,%1,%2,%3};" \
        : "+f"((c)[0]), "+f"((c)[1]), "+f"((c)[2]), "+f"((c)[3]) \
        : "r"((a)[0]), "r"((a)[1]), "r"((a)[2]), "r"((a)[3]), \
          "r"((b)[0]), "r"((b)[1]))

#define LDSM_X4(r0, r1, r2, r3, addr) \
    asm volatile("ldmatrix.sync.aligned.m8n8.x4.shared.b16 {%0,%1,%2,%3}, [%4];" \
                 : "=r"(r0), "=r"(r1), "=r"(r2), "=r"(r3) : "r"(addr))

// ---------------------------------------------------------------------------
// transpose h (B,C,H,W)->(N,C): fp32 + fp16 copies, fused sum(h^2) partial
__global__ void prep_h_kernel(const float* __restrict__ h) {
    __shared__ float tile[32][33];
    __shared__ float rsm[8];
    int b = blockIdx.z, ct = blockIdx.y, st = blockIdx.x;
    int c0 = ct * 32, s0 = st * 32;
    int tx = threadIdx.x, ty = threadIdx.y;
    int t = ty * 32 + tx;

    const float* src = h + ((size_t)b * C_DIM + c0) * 1024 + s0;
    float sq = 0.f;
    #pragma unroll
    for (int i = 0; i < 32; i += 8) {
        float v = src[(size_t)(ty + i) * 1024 + tx];
        tile[ty + i][tx] = v;
        sq = fmaf(v, v, sq);
    }
    __syncthreads();
    size_t rowbase = (size_t)b * 1024 + s0;
    #pragma unroll
    for (int i = 0; i < 32; i += 8) {
        float x = tile[tx][ty + i];
        size_t idx = (rowbase + ty + i) * C_DIM + c0 + tx;
        g_hflat[idx] = x;
        g_A16[idx]   = __float2half_rn(x);
    }
    #pragma unroll
    for (int o = 16; o > 0; o >>= 1) sq += __shfl_down_sync(0xFFFFFFFFu, sq, o);
    if ((t & 31) == 0) rsm[t >> 5] = sq;
    __syncthreads();
    if (t == 0) {
        float tot = 0.f;
        #pragma unroll
        for (int i = 0; i < 8; i++) tot += rsm[i];
        g_partial[(b * 8 + ct) * 32 + st] = tot;
    }
}

__global__ void prep_emb_kernel(const float* __restrict__ emb) {
    int v = blockIdx.x, t = threadIdx.x;
    float x = emb[v * C_DIM + t];
    g_B16[v * C_DIM + t] = __float2half_rn(x);

    float s = x * x;
    __shared__ float sm[8];
    #pragma unroll
    for (int o = 16; o > 0; o >>= 1) s += __shfl_down_sync(0xFFFFFFFFu, s, o);
    if ((t & 31) == 0) sm[t >> 5] = s;
    __syncthreads();
    if (t == 0) {
        float tot = 0.f;
        #pragma unroll
        for (int i = 0; i < 8; i++) tot += sm[i];
        g_halfnorm[v] = 0.5f * tot;
        g_enorm[v]    = sqrtf(tot);
    }
}

__global__ void xnorm_kernel() {
    int w = threadIdx.x >> 5, lane = threadIdx.x & 31;
    int r = blockIdx.x * 8 + w;
    const float* xr = g_hflat + (size_t)r * C_DIM;
    float p = 0.f;
    #pragma unroll
    for (int i = 0; i < 8; i++) { float x = xr[lane + i * 32]; p = fmaf(x, x, p); }
    #pragma unroll
    for (int o = 16; o > 0; o >>= 1) p += __shfl_xor_sync(0xFFFFFFFFu, p, o);
    if (lane == 0) g_xnorm[r] = sqrtf(p);
}

// ---------------------------------------------------------------------------
// Fused mma.sync GEMM (ldmatrix fragments) + register filter + exact rescore.
// 256 CTAs (M tile 64) x 256 threads (8 warps: wm in {0,1} x wn in {0..3}).
// Warp tile 32x32. v-tile N=128, K chunks of 128 (2 per v-tile).
#define MTILE 64
#define LDA   264        // halfs: row stride 528B == 16 mod 128 -> LDSM conflict-free
#define LDB   136        // halfs: row stride 272B == 16 mod 128 -> LDSM conflict-free
#define CAP   32
#define OFF_A    0                        // 64*264*2   = 33792
#define OFF_B    33792                    // 2*128*136*2= 69632
#define OFF_XN   103424                   // 64 floats
#define OFF_ML   103680                   // 64 u32
#define OFF_CNT  103936                   // 64 ints
#define OFF_CAND 104192                   // 64*32 u16  = 4096
#define SMEM_P1  108288

__global__ __launch_bounds__(256, 2) void pass1_kernel(const float* __restrict__ emb) {
    extern __shared__ char smem[];
    const uint32_t sb = smem_u32(smem);
    float*    XN  = reinterpret_cast<float*>(smem + OFF_XN);
    unsigned* ML  = reinterpret_cast<unsigned*>(smem + OFF_ML);
    int*      CNT = reinterpret_cast<int*>(smem + OFF_CNT);
    unsigned short* CAND = reinterpret_cast<unsigned short*>(smem + OFF_CAND);

    const int tid = threadIdx.x;
    const int w = tid >> 5, lane = tid & 31;
    const int wm = w & 1, wn = w >> 1;
    const int m0 = blockIdx.x * MTILE;
    const int lg = lane >> 2;        // group id 0..7
    const int lq = lane & 3;         // quad id 0..3

    if (tid < 64) {
        XN[tid] = __ldg(&g_xnorm[m0 + tid]);
        ML[tid] = 0u;                 // maps to "below -inf"
        CNT[tid] = 0;
    }

    // ldmatrix lane-address offsets (bytes)
    // A x4: matrices = (rows 0-7,k), (rows 8-15,k), (rows 0-7,k+8), (rows 8-15,k+8)
    const uint32_t aLane = (uint32_t)(((lane & 15) * LDA + (lane >> 4) * 8) * 2);
    const uint32_t aBase0 = sb + OFF_A + (uint32_t)(wm * 32 * LDA * 2) + aLane;
    // B x4: matrices = (n 0-7,k), (n 0-7,k+8), (n 8-15,k), (n 8-15,k+8)
    const uint32_t bLane = (uint32_t)(
        ((((lane & 7) | ((lane >> 4) << 3)) * LDB) + ((lane >> 3) & 1) * 8) * 2);

    // loader constants
    const int ldr = tid >> 4, ldq = tid & 15;          // B tile: 16 rows/iter
    const int lar = tid >> 5, laq = tid & 31;          // A tile: 8 rows/iter

    // resident A tile: 64 rows x 512B
    #pragma unroll
    for (int i = 0; i < 8; i++) {
        int r = lar + i * 8;
        CP_ASYNC16(sb + OFF_A + (uint32_t)(r * LDA * 2 + laq * 16),
                   g_A16 + (size_t)(m0 + r) * C_DIM + laq * 8);
    }
    CP_COMMIT();
    // B chunk 0 into stage 0 (128 rows x 256B)
    #pragma unroll
    for (int i = 0; i < 8; i++) {
        int r = ldr + i * 16;
        CP_ASYNC16(sb + OFF_B + (uint32_t)(r * LDB * 2 + ldq * 16),
                   g_B16 + (size_t)r * C_DIM + ldq * 8);
    }
    CP_COMMIT();

    float acc[2][4][4];

    for (int gc = 0; gc < 64; gc++) {
        const int kc = gc & 1;
        const int v0 = (gc >> 1) << 7;

        // prefetch next chunk into the other stage (end-of-loop barrier
        // separates the reads of the stage being overwritten)
        if (gc < 63) {
            const int ng = gc + 1;
            const int nv0 = (ng >> 1) << 7;
            const int nk0 = (ng & 1) * 128;
            const uint32_t dstb = sb + OFF_B + (uint32_t)((ng & 1) * (128 * LDB * 2));
            #pragma unroll
            for (int i = 0; i < 8; i++) {
                int r = ldr + i * 16;
                CP_ASYNC16(dstb + (uint32_t)(r * LDB * 2 + ldq * 16),
                           g_B16 + (size_t)(nv0 + r) * C_DIM + nk0 + ldq * 8);
            }
            CP_COMMIT();
            CP_WAIT1();
        } else {
            CP_WAIT0();
        }
        __syncthreads();

        if (kc == 0) {
            #pragma unroll
            for (int mf = 0; mf < 2; mf++)
                #pragma unroll
                for (int nf = 0; nf < 4; nf++)
                    #pragma unroll
                    for (int i = 0; i < 4; i++) acc[mf][nf][i] = 0.f;
        }

        const uint32_t bStage = sb + OFF_B + (uint32_t)((gc & 1) * (128 * LDB * 2))
                              + (uint32_t)(wn * 32 * LDB * 2) + bLane;
        const uint32_t aK = (uint32_t)(kc * 128 * 2);

        #pragma unroll
        for (int ks = 0; ks < 8; ks++) {
            uint32_t a[2][4], b[4][2];
            const uint32_t ka = aK + (uint32_t)(ks * 32);    // ks*16 halfs
            const uint32_t kb = (uint32_t)(ks * 32);
            LDSM_X4(a[0][0], a[0][1], a[0][2], a[0][3], aBase0 + ka);
            LDSM_X4(a[1][0], a[1][1], a[1][2], a[1][3],
                    aBase0 + (uint32_t)(16 * LDA * 2) + ka);
            LDSM_X4(b[0][0], b[0][1], b[1][0], b[1][1], bStage + kb);
            LDSM_X4(b[2][0], b[2][1], b[3][0], b[3][1],
                    bStage + (uint32_t)(16 * LDB * 2) + kb);
            #pragma unroll
            for (int mf = 0; mf < 2; mf++)
                #pragma unroll
                for (int nf = 0; nf < 4; nf++)
                    MMA16816(acc[mf][nf], a[mf], b[nf]);
        }

        if (kc == 1) {
            // ---- register epilogue for v-tile [v0, v0+128) ----
            // acc[mf][nf] rows: wm*32+mf*16+lg (+8); cols: wn*32+nf*8+lq*2 (+1)
            const int rbase = wm * 32 + lg;
            #pragma unroll
            for (int mf = 0; mf < 2; mf++) {
                #pragma unroll
                for (int hh = 0; hh < 2; hh++) {
                    const int row = rbase + mf * 16 + hh * 8;
                    const float mx = MCOEF * XN[row];
                    float lowmax = -FLT_MAX;
                    #pragma unroll
                    for (int nf = 0; nf < 4; nf++) {
                        const int col = wn * 32 + nf * 8 + lq * 2;
                        float2 hn2 = *reinterpret_cast<const float2*>(g_halfnorm + v0 + col);
                        float2 en2 = *reinterpret_cast<const float2*>(g_enorm + v0 + col);
                        float s0 = acc[mf][nf][2 * hh]     - hn2.x;
                        float s1 = acc[mf][nf][2 * hh + 1] - hn2.y;
                        float me0 = fmaf(mx, en2.x, SLK);
                        float me1 = fmaf(mx, en2.y, SLK);
                        lowmax = fmaxf(lowmax, fmaxf(s0 - me0, s1 - me1));
                        acc[mf][nf][2 * hh]     = s0 + me0;   // upper bound
                        acc[mf][nf][2 * hh + 1] = s1 + me1;
                    }
                    atomicMax(&ML[row], fmap(lowmax));
                    // read back a (possibly stale-lower) threshold — always a
                    // valid lower bound on the final max-lower, so the filter
                    // keeps a superset of the true argmax candidates.
                    const unsigned thr = ML[row];
                    #pragma unroll
                    for (int nf = 0; nf < 4; nf++) {
                        const int col = v0 + wn * 32 + nf * 8 + lq * 2;
                        if (fmap(acc[mf][nf][2 * hh]) >= thr) {
                            int p = atomicAdd(&CNT[row], 1);
                            if (p < CAP) CAND[row * CAP + p] = (unsigned short)col;
                        }
                        if (fmap(acc[mf][nf][2 * hh + 1]) >= thr) {
                            int p = atomicAdd(&CNT[row], 1);
                            if (p < CAP) CAND[row * CAP + p] = (unsigned short)(col + 1);
                        }
                    }
                }
            }
        }
        // separate this iteration's B-stage reads from the next prefetch writes
        __syncthreads();
    }

    // ---- exact fp32 rescore of candidates (warp per row) ----
    for (int rr = 0; rr < 8; rr++) {
        const int row = rr * 8 + w;
        const int r = m0 + row;
        float xr[8];
        const float* xp = g_hflat + (size_t)r * C_DIM;
        #pragma unroll
        for (int i = 0; i < 8; i++) xr[i] = xp[lane + i * 32];

        const int n = CNT[row];
        const bool full = (n > CAP);
        const int total = full ? VOCAB : n;

        float best = -FLT_MAX;
        int bidx = VOCAB;
        for (int j = 0; j < total; j++) {
            const int v = full ? j : (int)CAND[row * CAP + j];
            const float* ev = emb + (size_t)v * C_DIM;
            float p = 0.f;
            #pragma unroll
            for (int i = 0; i < 8; i++) p = fmaf(xr[i], __ldg(&ev[lane + i * 32]), p);
            #pragma unroll
            for (int o = 16; o > 0; o >>= 1) p += __shfl_xor_sync(0xFFFFFFFFu, p, o);
            const float s = p - __ldg(&g_halfnorm[v]);
            if (s > best || (s == best && v < bidx)) { best = s; bidx = v; }
        }
        if (lane == 0) { g_bestscore[r] = best; g_bestidx[r] = bidx; }
    }
}

// ---------------------------------------------------------------------------
__global__ void gather_kernel(const float* __restrict__ emb, float* __restrict__ out) {
    int bc = blockIdx.x;
    int b = bc >> 8, c = bc & 255;
    int t = threadIdx.x;
    #pragma unroll
    for (int u = 0; u < 4; u++) {
        int sp = t + u * 256;
        int n = b * 1024 + sp;
        out[(size_t)bc * 1024 + sp] = __ldg(&emb[(size_t)g_bestidx[n] * C_DIM + c]);
    }
}

__global__ void indices_kernel(float* __restrict__ out) {
    int n = blockIdx.x * 256 + threadIdx.x;
    out[4194304 + n] = (float)g_bestidx[n];
}

__global__ void loss_kernel(float* __restrict__ out) {
    __shared__ float sm[256];
    int t = threadIdx.x;
    float s1 = 0.f, s2 = 0.f;
    for (int i = t; i < 4096; i += 256)  s1 += g_partial[i];
    for (int i = t; i < N_VEC; i += 256) s2 += g_bestscore[i];
    sm[t] = s1 - 2.f * s2;
    __syncthreads();
    #pragma unroll
    for (int o = 128; o > 0; o >>= 1) {
        if (t < o) sm[t] += sm[t + o];
        __syncthreads();
    }
    if (t == 0) out[4210688] = sm[0] / 4194304.f;
}

// ---------------------------------------------------------------------------
extern "C" void kernel_launch(void* const* d_in, const int* in_sizes, int n_in,
                              void* d_out, int out_size) {
    const float* h   = (const float*)d_in[0];
    const float* emb = (const float*)d_in[1];
    float* out = (float*)d_out;

    static bool attr_set = false;
    if (!attr_set) {
        cudaFuncSetAttribute(pass1_kernel,
                             cudaFuncAttributeMaxDynamicSharedMemorySize, SMEM_P1);
        attr_set = true;
    }

    dim3 tgrid(32, 8, 16), tblk(32, 8);
    prep_h_kernel<<<tgrid, tblk>>>(h);
    prep_emb_kernel<<<VOCAB, 256>>>(emb);
    xnorm_kernel<<<N_VEC / 8, 256>>>();

    pass1_kernel<<<N_VEC / MTILE, 256, SMEM_P1>>>(emb);

    gather_kernel<<<4096, 256>>>(emb, out);
    indices_kernel<<<N_VEC / 256, 256>>>(out);
    loss_kernel<<<1, 256>>>(out);
}